// round 16
// baseline (speedup 1.0000x reference)
#include <cuda_runtime.h>
#include <math_constants.h>

#define KVOL 27
#define C8   12                 // 96 channels = 12 x 8-float (32B) chunks
#define C4   24                 // row stride in float4 units
#define RPB  32                 // rows per block: 12*32 = 384 threads
#define NTHREADS (C8 * RPB)

// 256-bit gather load with direct evict_last L2 modifier (v8.b32 form is the
// one ptxas documents as supporting .L2::evict_last on sm_100a).
__device__ __forceinline__ void ldg256(const float4* p, float4& a, float4& b) {
    unsigned r0,r1,r2,r3,r4,r5,r6,r7;
    asm("ld.global.nc.L2::evict_last.v8.b32 {%0,%1,%2,%3,%4,%5,%6,%7}, [%8];"
        : "=r"(r0),"=r"(r1),"=r"(r2),"=r"(r3),
          "=r"(r4),"=r"(r5),"=r"(r6),"=r"(r7) : "l"(p));
    a.x=__uint_as_float(r0); a.y=__uint_as_float(r1);
    a.z=__uint_as_float(r2); a.w=__uint_as_float(r3);
    b.x=__uint_as_float(r4); b.y=__uint_as_float(r5);
    b.z=__uint_as_float(r6); b.w=__uint_as_float(r7);
}

__device__ __forceinline__ void vmax(float4& m, const float4 v) {
    m.x = fmaxf(m.x, v.x);
    m.y = fmaxf(m.y, v.y);
    m.z = fmaxf(m.z, v.z);
    m.w = fmaxf(m.w, v.w);
}

// Gather B neighbors (32B each, indices from smem) with all B in flight.
template <int B>
__device__ __forceinline__ void gather_batch(const float4* __restrict__ feat,
                                             const int* __restrict__ s_idx, int kb,
                                             float4& ma, float4& mb) {
    unsigned idx[B];
    #pragma unroll
    for (int j = 0; j < B; ++j)
        idx[j] = (unsigned)s_idx[kb + j];              // LDS broadcast
    float4 va[B], vb[B];
    #pragma unroll
    for (int j = 0; j < B; ++j)                        // B x 32B outstanding
        ldg256(feat + (size_t)idx[j] * C4, va[j], vb[j]);
    #pragma unroll
    for (int j = 0; j < B; ++j) { vmax(ma, va[j]); vmax(mb, vb[j]); }
}

// 256-bit-load geometry: 12 lanes/row x 32B halves the LDG instruction count
// per row (half the L1tex wavefront-queue entries per useful byte) while
// keeping in-flight bytes at/above the converged float4 optimum.
__global__ __launch_bounds__(NTHREADS, 2)
void sparse_maxpool_kernel(const float4* __restrict__ in_feat,
                           const void* __restrict__ nmap,
                           float4* __restrict__ out,
                           int n_out, int n_in_rows) {
    __shared__ int s_bad;
    __shared__ int s_idx[RPB][KVOL];                   // 864 ints = 3.4 KB

    int t = threadIdx.y * C8 + threadIdx.x;
    if (t == 0) s_bad = 0;
    __syncthreads();
    if (t < 64) {                                      // dtype probe (512B, L2-hot)
        const long long* p = (const long long*)nmap;
        long long v = p[t];
        if (v < 0 || v >= (long long)n_in_rows) atomicOr(&s_bad, 1);
    }
    __syncthreads();
    int is64 = (s_bad == 0);

    int row0 = blockIdx.x * RPB;
    int nrows = min(RPB, n_out - row0);
    int nelem = nrows * KVOL;

    // ---- Cooperative, coalesced index staging into smem ----
    if (is64) {
        const long long* nmb = (const long long*)nmap + (size_t)row0 * KVOL;
        for (int e = t; e < nelem; e += NTHREADS)
            s_idx[e / KVOL][e % KVOL] = (int)__ldcs(&nmb[e]);
    } else {
        const int* nmb = (const int*)nmap + (size_t)row0 * KVOL;
        for (int e = t; e < nelem; e += NTHREADS)
            s_idx[e / KVOL][e % KVOL] = __ldcs(&nmb[e]);
    }
    __syncthreads();

    int row = row0 + threadIdx.y;
    if (row >= n_out) return;
    int c8 = threadIdx.x;                              // 0..11 (32B chunk index)

    const float4* feat_c = in_feat + c8 * 2;           // 2 float4 per chunk
    const int* my_idx = s_idx[threadIdx.y];

    float4 ma = make_float4(-CUDART_INF_F, -CUDART_INF_F, -CUDART_INF_F, -CUDART_INF_F);
    float4 mb = ma;
    gather_batch<7>(feat_c, my_idx, 0,  ma, mb);       // waves of <=7:
    gather_batch<7>(feat_c, my_idx, 7,  ma, mb);       // 7 x 32B = 224B/thread
    gather_batch<7>(feat_c, my_idx, 14, ma, mb);       // in flight
    gather_batch<6>(feat_c, my_idx, 21, ma, mb);

    float4* outp = out + (size_t)row * C4 + c8 * 2;
    __stcs(outp,     ma);                              // streaming stores
    __stcs(outp + 1, mb);
}

extern "C" void kernel_launch(void* const* d_in, const int* in_sizes, int n_in,
                              void* d_out, int out_size) {
    const float4* in_feat = (const float4*)d_in[0];
    const void*   nmap    = (const void*)d_in[1];
    float4*       out     = (float4*)d_out;

    int nmap_elems = in_sizes[1];                      // N_OUT * KVOL
    int n_out      = nmap_elems / KVOL;                // 100000
    int n_in_rows  = in_sizes[0] / 96;                 // 400000

    dim3 block(C8, RPB);
    int grid = (n_out + RPB - 1) / RPB;
    sparse_maxpool_kernel<<<grid, block>>>(in_feat, nmap, out, n_out, n_in_rows);
}

// round 17
// speedup vs baseline: 1.0455x; 1.0455x over previous
#include <cuda_runtime.h>
#include <math_constants.h>

#define KVOL 27
#define C4   24                 // 96 channels = 24 float4
#define RPB  16                 // rows per block: 24*16 = 384 threads

// L2 policy: keep in_feat lines resident (evict-last priority).
__device__ __forceinline__ unsigned long long mk_keep_policy() {
    unsigned long long pol;
    asm("createpolicy.fractional.L2::evict_last.b64 %0, 1.0;" : "=l"(pol));
    return pol;
}

// Gather load: bypass L1 (.cg) + evict_last L2 policy.
__device__ __forceinline__ float4 ldg_gather(const float4* p, unsigned long long pol) {
    float4 v;
    asm("ld.global.cg.L2::cache_hint.v4.f32 {%0,%1,%2,%3}, [%4], %5;"
        : "=f"(v.x), "=f"(v.y), "=f"(v.z), "=f"(v.w) : "l"(p), "l"(pol));
    return v;
}

__device__ __forceinline__ void vmax(float4& m, const float4 v) {
    m.x = fmaxf(m.x, v.x);
    m.y = fmaxf(m.y, v.y);
    m.z = fmaxf(m.z, v.z);
    m.w = fmaxf(m.w, v.w);
}

// Gather B neighbors with all B loads in flight, then reduce.
template <int B, typename IDX>
__device__ __forceinline__ void gather_batch(const float4* __restrict__ feat,
                                             const IDX* __restrict__ nm, int kb,
                                             float4& m, unsigned long long pol) {
    int idx[B];
    #pragma unroll
    for (int j = 0; j < B; ++j)
        idx[j] = (int)__ldcs(&nm[kb + j]);             // streaming index read
    float4 v[B];
    #pragma unroll
    for (int j = 0; j < B; ++j)                        // B x 16B outstanding
        v[j] = ldg_gather(feat + (long long)idx[j] * C4, pol);
    #pragma unroll
    for (int j = 0; j < B; ++j)
        vmax(m, v[j]);
}

template <typename IDX>
__device__ __forceinline__ void pool_row(const float4* __restrict__ feat,
                                         const IDX* __restrict__ nm,
                                         float4* __restrict__ outp) {
    const unsigned long long pol = mk_keep_policy();
    float4 m = make_float4(-CUDART_INF_F, -CUDART_INF_F, -CUDART_INF_F, -CUDART_INF_F);
    gather_batch<9>(feat, nm, 0,  m, pol);             // 3 waves of 9:
    gather_batch<9>(feat, nm, 9,  m, pol);             // ~330 outstanding
    gather_batch<9>(feat, nm, 18, m, pol);             // sectors/SM at 36 warps
    __stcs(outp, m);                                   // streaming store
}

// Converged optimum of the 16-round search: 36 warps/SM (minBlocks=3,
// regs=56), 24-lane float4 gathers, 9-deep MLP waves. Runs the irreducible
// 1.04 GB logical gather at ~97% of the L2 sector-path cap with DRAM at its
// random-pattern ceiling.
__global__ __launch_bounds__(C4 * RPB, 3)
void sparse_maxpool_kernel(const float4* __restrict__ in_feat,
                           const void* __restrict__ nmap,
                           float4* __restrict__ out,
                           int n_out, int n_in_rows) {
    // ---- Inline dtype detection (per block; 512B probe, L2-hot) ----
    __shared__ int s_bad;
    int t = threadIdx.y * C4 + threadIdx.x;
    if (t == 0) s_bad = 0;
    __syncthreads();
    if (t < 64) {
        const long long* p = (const long long*)nmap;
        long long v = p[t];
        if (v < 0 || v >= (long long)n_in_rows) atomicOr(&s_bad, 1);
    }
    __syncthreads();
    int is64 = (s_bad == 0);

    int row = blockIdx.x * RPB + threadIdx.y;
    if (row >= n_out) return;
    int c4 = threadIdx.x;                              // 0..23

    const float4* feat_c = in_feat + c4;
    float4* outp = out + (long long)row * C4 + c4;

    if (is64) {
        const long long* nm = (const long long*)nmap + (long long)row * KVOL;
        pool_row(feat_c, nm, outp);
    } else {
        const int* nm = (const int*)nmap + (long long)row * KVOL;
        pool_row(feat_c, nm, outp);
    }
}

extern "C" void kernel_launch(void* const* d_in, const int* in_sizes, int n_in,
                              void* d_out, int out_size) {
    const float4* in_feat = (const float4*)d_in[0];
    const void*   nmap    = (const void*)d_in[1];
    float4*       out     = (float4*)d_out;

    int nmap_elems = in_sizes[1];                      // N_OUT * KVOL
    int n_out      = nmap_elems / KVOL;                // 100000
    int n_in_rows  = in_sizes[0] / 96;                 // 400000

    dim3 block(C4, RPB);
    int grid = (n_out + RPB - 1) / RPB;
    sparse_maxpool_kernel<<<grid, block>>>(in_feat, nmap, out, n_out, n_in_rows);
}